// round 13
// baseline (speedup 1.0000x reference)
#include <cuda_runtime.h>
#include <math.h>

// Problem-instance constants (setup_inputs: b=2, h=240, w=320, n=2*h*w)
#define BB 2
#define NN 153600
#define HH 240
#define WW 320
#define HWp (HH * WW)
#define PLANE (BB * HWp)
#define ZNEAR 0.1f
#define ZFAR 1000.0f

#define T1 256
#define PB 150                  // blocks per batch: 150 * 256 thr * 4 pts = NN
#define QB 75                   // fill blocks per batch: 75 * 256 = 19200 quads

// Scratch (__device__ globals; no allocations allowed)
__device__ __align__(16) unsigned g_key[PLANE];      // packed (dq<<18|i)+1
__device__ __align__(16) float    g_dep[PLANE];      // dense depth plane (iter0)
__device__ __align__(16) float4   g_rec[PLANE];      // cf,r,g,b (UNINIT for empty px)
__device__ __align__(16) float    g_dep2[PLANE];     // depth after iter1
__device__ __align__(16) float4   g_rec2[PLANE];     // channels after iter1
__device__ __align__(16) float    g_pz [BB * NN];
__device__ __align__(16) unsigned g_pxy[BB * NN];
__device__ float g_bmn[BB * PB];
__device__ float g_bmx[BB * PB];

__device__ __forceinline__ float4 f4max(float4 a, float4 b) {
    return make_float4(fmaxf(a.x, b.x), fmaxf(a.y, b.y),
                       fmaxf(a.z, b.z), fmaxf(a.w, b.w));
}

// ---------------------------------------------------------------------------
// K1 (per batch): zero this batch's depth+key planes; transform 4 pts/thread;
// per-block minmax.
// ---------------------------------------------------------------------------
__global__ __launch_bounds__(T1)
void k_prep(const float* __restrict__ pp, const float* __restrict__ conf,
            const float* __restrict__ pose, const float* __restrict__ Kc, int b)
{
    __shared__ float sred[T1 / 32];
    const int tid = threadIdx.x;
    const int gt  = blockIdx.x * T1 + tid;     // 0 .. 38399

    if (gt < HWp / 4) {                         // 19200 uint4/float4 per batch
        ((float4*)g_dep)[b * (HWp / 4) + gt] = make_float4(0.f, 0.f, 0.f, 0.f);
        ((uint4*)g_key)[b * (HWp / 4) + gt]  = make_uint4(0u, 0u, 0u, 0u);
    }

    const int i  = gt * 4;                      // batch-local point index
    const int p4 = b * NN + i;

    const float* ppb = pp + (size_t)b * 7 * NN;
    float4 c0 = *(const float4*)(ppb + 0 * NN + i);
    float4 c1 = *(const float4*)(ppb + 1 * NN + i);
    float4 c2 = *(const float4*)(ppb + 2 * NN + i);
    float4 c3 = *(const float4*)(ppb + 3 * NN + i);
    float4 cf4 = *(const float4*)(conf + (size_t)b * NN + i);

    const float* P  = pose + b * 16;
    const float* Kb = Kc + b * 9;
    float fx = Kb[0], cx = Kb[2], fy = Kb[4], cy = Kb[5];

    float zz[4]; unsigned px[4];
    float mn = 3.0e38f, mx = 0.0f;
    float p0a[4] = {c0.x, c0.y, c0.z, c0.w};
    float p1a[4] = {c1.x, c1.y, c1.z, c1.w};
    float p2a[4] = {c2.x, c2.y, c2.z, c2.w};
    float p3a[4] = {c3.x, c3.y, c3.z, c3.w};
    float cfa[4] = {cf4.x, cf4.y, cf4.z, cf4.w};
#pragma unroll
    for (int j = 0; j < 4; j++) {
        float pc0 = P[0] * p0a[j] + P[1] * p1a[j] + P[2]  * p2a[j] + P[3]  * p3a[j];
        float pc1 = P[4] * p0a[j] + P[5] * p1a[j] + P[6]  * p2a[j] + P[7]  * p3a[j];
        float pc2 = P[8] * p0a[j] + P[9] * p1a[j] + P[10] * p2a[j] + P[11] * p3a[j];
        float z = fabsf(pc2);
        float xc = __fadd_rn(__fdiv_rn(__fmul_rn(pc0, fx), z), cx);
        float yc = __fadd_rn(__fdiv_rn(__fmul_rn(pc1, fy), z), cy);
        int x = (int)rintf(xc);
        int y = (int)rintf(yc);
        bool valid = !(x < 0 || x >= WW || y < 0 || y >= HH ||
                       z < ZNEAR || z > ZFAR || cfa[j] <= 0.0f);
        zz[j] = z;
        px[j] = valid ? (unsigned)(y * WW + x) : 0xFFFFFFFFu;
        if (valid) {
            float inv = __fdiv_rn(1.0f, z);
            mn = fminf(mn, inv);
            mx = fmaxf(mx, inv);
        }
    }
    *(float4*)(g_pz + p4) = make_float4(zz[0], zz[1], zz[2], zz[3]);
    *(uint4*)(g_pxy + p4) = make_uint4(px[0], px[1], px[2], px[3]);

    const int lane = tid & 31, wid = tid >> 5;
#pragma unroll
    for (int s = 16; s > 0; s >>= 1) mn = fminf(mn, __shfl_down_sync(0xFFFFFFFFu, mn, s));
    if (lane == 0) sred[wid] = mn;
    __syncthreads();
    if (wid == 0) {
        float w = (lane < T1 / 32) ? sred[lane] : 3.0e38f;
#pragma unroll
        for (int s = 4; s > 0; s >>= 1) w = fminf(w, __shfl_down_sync(0xFFFFFFFFu, w, s));
        if (lane == 0) g_bmn[b * PB + blockIdx.x] = w;
    }
    __syncthreads();
#pragma unroll
    for (int s = 16; s > 0; s >>= 1) mx = fmaxf(mx, __shfl_down_sync(0xFFFFFFFFu, mx, s));
    if (lane == 0) sred[wid] = mx;
    __syncthreads();
    if (wid == 0) {
        float w = (lane < T1 / 32) ? sred[lane] : 0.0f;
#pragma unroll
        for (int s = 4; s > 0; s >>= 1) w = fmaxf(w, __shfl_down_sync(0xFFFFFFFFu, w, s));
        if (lane == 0) g_bmx[b * PB + blockIdx.x] = w;
    }
}

// ---------------------------------------------------------------------------
// K2 (per batch): finalize batch minmax; scatter atomicMax keys.
// ---------------------------------------------------------------------------
__global__ __launch_bounds__(T1)
void k_scatter(int b)
{
    __shared__ float sbc[2];
    const int tid = threadIdx.x;
    const int lane = tid & 31, wid = tid >> 5;

    if (wid < 2) {
        bool ismax = wid;
        float v = ismax ? 0.0f : 3.0e38f;
        for (int k = b * PB + lane; k < (b + 1) * PB; k += 32) {
            float u = ismax ? g_bmx[k] : g_bmn[k];
            v = ismax ? fmaxf(v, u) : fminf(v, u);
        }
#pragma unroll
        for (int s = 16; s > 0; s >>= 1) {
            float u = __shfl_down_sync(0xFFFFFFFFu, v, s);
            v = ismax ? fmaxf(v, u) : fminf(v, u);
        }
        if (lane == 0) sbc[wid] = ismax ? fmaxf(v, 1.0e-10f) : fminf(v, 1.0e10f);
    }
    __syncthreads();
    const float dmn = sbc[0];
    const float rng = __fsub_rn(sbc[1], dmn);

    const int gt = blockIdx.x * T1 + tid;
    const int i  = gt * 4;
    const int p4 = b * NN + i;
    uint4  px4 = *(const uint4*)(g_pxy + p4);
    float4 pz4 = *(const float4*)(g_pz + p4);
    unsigned pxa[4] = {px4.x, px4.y, px4.z, px4.w};
    float    zza[4] = {pz4.x, pz4.y, pz4.z, pz4.w};
#pragma unroll
    for (int j = 0; j < 4; j++) {
        if (pxa[j] == 0xFFFFFFFFu) continue;
        float inv = __fdiv_rn(1.0f, zza[j]);
        float t = __fmul_rn(__fdiv_rn(__fsub_rn(inv, dmn), rng), 63.0f);
        int dq = (int)t;
        unsigned key = ((((unsigned)dq) << 18) | (unsigned)(i + j)) + 1u;
        atomicMax(&g_key[b * HWp + pxa[j]], key);
    }
}

// ---------------------------------------------------------------------------
// K3 (per batch): resolve — winners write depth + record at flipped position.
// ---------------------------------------------------------------------------
__global__ __launch_bounds__(T1)
void k_resolve(const float* __restrict__ pp, const float* __restrict__ conf, int b)
{
    const int tid = threadIdx.x;
    const int gt  = blockIdx.x * T1 + tid;
    const int i   = gt * 4;
    const int p4  = b * NN + i;

    uint4  px4 = *(const uint4*)(g_pxy + p4);
    float4 pz4 = *(const float4*)(g_pz + p4);
    unsigned pxa[4] = {px4.x, px4.y, px4.z, px4.w};
    float    zza[4] = {pz4.x, pz4.y, pz4.z, pz4.w};

    unsigned ky[4];
#pragma unroll
    for (int j = 0; j < 4; j++)
        ky[j] = (pxa[j] != 0xFFFFFFFFu) ? g_key[b * HWp + pxa[j]] : 0u;

    const float* ppb = pp + (size_t)b * 7 * NN;
    float4 cf4 = *(const float4*)(conf + (size_t)b * NN + i);
    float4 r04 = *(const float4*)(ppb + 4 * NN + i);
    float4 r14 = *(const float4*)(ppb + 5 * NN + i);
    float4 r24 = *(const float4*)(ppb + 6 * NN + i);
    float cfa[4] = {cf4.x, cf4.y, cf4.z, cf4.w};
    float r0a[4] = {r04.x, r04.y, r04.z, r04.w};
    float r1a[4] = {r14.x, r14.y, r14.z, r14.w};
    float r2a[4] = {r24.x, r24.y, r24.z, r24.w};

#pragma unroll
    for (int j = 0; j < 4; j++) {
        if (pxa[j] == 0xFFFFFFFFu) continue;
        if (((ky[j] - 1u) & 0x3FFFFu) != (unsigned)(i + j)) continue;
        unsigned pxy = pxa[j];
        int y = (int)(pxy / WW), x = (int)(pxy - (unsigned)y * WW);
        int rf = HH - 1 - y;
        int pix = b * HWp + rf * WW + x;
        g_dep[pix] = zza[j];
        g_rec[pix] = make_float4(fmaxf(cfa[j], 0.0f), r0a[j], r1a[j], r2a[j]);
    }
}

// ---------------------------------------------------------------------------
// Fill: one hole-fill iteration, 4 pixels (one aligned quad) per thread.
// 0/1-mask conv (bit-identical to reference FMA loop); conv pads 0; values
// >= 0 so maxpool over in-bounds taps == max with zero floor.
// GATED=true: channel records valid only where depth>0 (iter-0 AoS).
// ---------------------------------------------------------------------------
template <bool GATED>
__device__ __forceinline__ void fill_quad(
    const float* __restrict__ dep, const float4* __restrict__ rec,
    int gy, int gx0, float* dout, float4* chout)
{
    float row[3][6];
#pragma unroll
    for (int r = 0; r < 3; r++) {
        int rr = gy - 1 + r;
        bool rv = (unsigned)rr < HH;
        float4 m = rv ? *(const float4*)(dep + rr * WW + gx0)
                      : make_float4(0.f, 0.f, 0.f, 0.f);
        row[r][1] = m.x; row[r][2] = m.y; row[r][3] = m.z; row[r][4] = m.w;
        row[r][0] = (rv && gx0 > 0)        ? dep[rr * WW + gx0 - 1] : 0.0f;
        row[r][5] = (rv && gx0 + 4 < WW)   ? dep[rr * WW + gx0 + 4] : 0.0f;
    }

    float4 myrec[4];
#pragma unroll
    for (int j = 0; j < 4; j++) myrec[j] = rec[gy * WW + gx0 + j];

#pragma unroll
    for (int j = 0; j < 4; j++) {
        float d0 = row[0][j], d1 = row[0][j+1], d2 = row[0][j+2];
        float d3 = row[1][j], d4 = row[1][j+1], d5 = row[1][j+2];
        float d6 = row[2][j], d7 = row[2][j+1], d8 = row[2][j+2];
        float s = d0 + d1 + d2 + d3 + d4 + d5 + d6 + d7 + d8;

        bool fill = false;
        if (s > 0.0f && d4 <= 0.0f) {
            float o0 = d0 + d3 + d6;
            float o1 = d6 + d7 + d8;
            float o2 = d2 + d5 + d8;
            float o3 = d0 + d1 + d2;
            float o4 = d3 + d6 + d7;
            float o5 = d5 + d7 + d8;
            float o6 = d1 + d2 + d5;
            float o7 = d0 + d1 + d3;
            float prod = ((((((o0 * o1) * o2) * o3) * o4) * o5) * o6) * o7;
            fill = fabsf(prod) > 1e-10f;
        }

        if (!fill) {
            dout[j] = d4;
            if (GATED && d4 <= 0.0f) chout[j] = make_float4(0.f, 0.f, 0.f, 0.f);
            else                     chout[j] = myrec[j];
        } else {
            float mxd = 0.0f;
            float4 cmx = make_float4(0.f, 0.f, 0.f, 0.f);
#pragma unroll
            for (int r = 0; r < 3; r++)
#pragma unroll
                for (int c = 0; c < 3; c++) {
                    float dv = row[r][j + c];
                    mxd = fmaxf(mxd, dv);
                    int rr = gy - 1 + r, cc = gx0 + j - 1 + c;
                    bool take = GATED ? (dv > 0.0f)
                                      : (((unsigned)rr < HH) & ((unsigned)cc < WW));
                    if (take) cmx = f4max(cmx, rec[rr * WW + cc]);
                }
            dout[j] = mxd; chout[j] = cmx;
        }
    }
}

// K4a (per batch): iteration 1, AoS -> AoS
__global__ __launch_bounds__(T1)
void k_fill_a(int b)
{
    int q   = blockIdx.x * T1 + threadIdx.x;     // quad index within batch
    int gy  = q / (WW / 4);
    int gx0 = (q - gy * (WW / 4)) * 4;

    float dout[4]; float4 chout[4];
    fill_quad<true>(g_dep + b * HWp, g_rec + b * HWp, gy, gx0, dout, chout);

    int base = b * HWp + gy * WW + gx0;
    *(float4*)(g_dep2 + base) = make_float4(dout[0], dout[1], dout[2], dout[3]);
#pragma unroll
    for (int j = 0; j < 4; j++) g_rec2[base + j] = chout[j];
}

// K4b (per batch): iteration 2, AoS -> planar dst
__global__ __launch_bounds__(T1)
void k_fill_b(float* __restrict__ dst, int b)
{
    int q   = blockIdx.x * T1 + threadIdx.x;
    int gy  = q / (WW / 4);
    int gx0 = (q - gy * (WW / 4)) * 4;

    float dout[4]; float4 chout[4];
    fill_quad<false>(g_dep2 + b * HWp, g_rec2 + b * HWp, gy, gx0, dout, chout);

    int rc = gy * WW + gx0;
    *(float4*)(dst + b * HWp + rc) =
        make_float4(dout[0], dout[1], dout[2], dout[3]);
    *(float4*)(dst + PLANE + b * HWp + rc) =
        make_float4(chout[0].x, chout[1].x, chout[2].x, chout[3].x);
    *(float4*)(dst + 2 * PLANE + (b * 3 + 0) * HWp + rc) =
        make_float4(chout[0].y, chout[1].y, chout[2].y, chout[3].y);
    *(float4*)(dst + 2 * PLANE + (b * 3 + 1) * HWp + rc) =
        make_float4(chout[0].z, chout[1].z, chout[2].z, chout[3].z);
    *(float4*)(dst + 2 * PLANE + (b * 3 + 2) * HWp + rc) =
        make_float4(chout[0].w, chout[1].w, chout[2].w, chout[3].w);
}

// ---------------------------------------------------------------------------
// Two independent per-batch chains on two streams; fork/join via events so
// graph capture records parallel branches. Stream/events are deliberately
// NOT destroyed: destroying a capture-participating stream invalidates the
// capture. (A handful of leaked handles across the few harness calls; no
// device allocations.) Work is identical and deterministic on every call.
// ---------------------------------------------------------------------------
extern "C" void kernel_launch(void* const* d_in, const int* in_sizes, int n_in,
                              void* d_out, int out_size)
{
    const float* pp      = (const float*)d_in[0];  // [b,7,n]
    const float* conf    = (const float*)d_in[1];  // [b,n]
    const float* pose    = (const float*)d_in[2];  // [b,4,4]
    const float* Kc      = (const float*)d_in[3];  // [b,3,3]
    (void)in_sizes; (void)n_in; (void)out_size;

    cudaStream_t s1 = 0;
    cudaEvent_t eRoot = 0, eJoin = 0;
    bool forked =
        (cudaStreamCreateWithFlags(&s1, cudaStreamNonBlocking) == cudaSuccess) &&
        (cudaEventCreateWithFlags(&eRoot, cudaEventDisableTiming) == cudaSuccess) &&
        (cudaEventCreateWithFlags(&eJoin, cudaEventDisableTiming) == cudaSuccess);

    if (forked) {
        cudaEventRecord(eRoot, 0);              // fork from default stream
        cudaStreamWaitEvent(s1, eRoot, 0);
    }

    for (int b = 0; b < BB; b++) {
        cudaStream_t s = (forked && b == 1) ? s1 : (cudaStream_t)0;
        k_prep   <<<PB, T1, 0, s>>>(pp, conf, pose, Kc, b);
        k_scatter<<<PB, T1, 0, s>>>(b);
        k_resolve<<<PB, T1, 0, s>>>(pp, conf, b);
        k_fill_a <<<QB, T1, 0, s>>>(b);
        k_fill_b <<<QB, T1, 0, s>>>((float*)d_out, b);
    }

    if (forked) {
        cudaEventRecord(eJoin, s1);             // join back to default stream
        cudaStreamWaitEvent(0, eJoin, 0);
    }
}

// round 14
// speedup vs baseline: 1.1125x; 1.1125x over previous
#include <cuda_runtime.h>
#include <math.h>

// Problem-instance constants (setup_inputs: b=2, h=240, w=320, n=2*h*w)
#define BB 2
#define NN 153600
#define HH 240
#define WW 320
#define HWp (HH * WW)
#define PLANE (BB * HWp)
#define ZNEAR 0.1f
#define ZFAR 1000.0f

#define T1 256
#define NB1 300                 // 300 blocks * 256 thr * 4 pts = 307200 points
#define BLKS_PER_B (NB1 / BB)   // 150

// Scratch (__device__ globals; no allocations allowed)
__device__ __align__(16) unsigned g_key[PLANE];      // packed (dq<<18|i)+1
__device__ __align__(16) float    g_dep[PLANE];      // dense depth plane (iter0)
__device__ __align__(16) float4   g_rec[PLANE];      // cf,r,g,b (UNINIT for empty px)
__device__ __align__(16) float    g_dep2[PLANE];     // depth after iter1
__device__ __align__(16) float4   g_rec2[PLANE];     // channels after iter1
__device__ __align__(16) float    g_pz [BB * NN];
__device__ __align__(16) unsigned g_pxy[BB * NN];
__device__ float g_bmn[NB1];
__device__ float g_bmx[NB1];
__device__ unsigned g_bar_count = 0;
__device__ unsigned g_bar_gen   = 0;

__device__ __forceinline__ float4 f4max(float4 a, float4 b) {
    return make_float4(fmaxf(a.x, b.x), fmaxf(a.y, b.y),
                       fmaxf(a.z, b.z), fmaxf(a.w, b.w));
}

// ---------------------------------------------------------------------------
// Software grid barrier (validated in R3: correct + replay-safe). All NB1
// blocks are co-resident: 256-thread / ~60-reg blocks fit >=4 per SM, and
// 300 <= 4*148. count self-resets; gen increments (relative compare).
// ---------------------------------------------------------------------------
__device__ __forceinline__ void gridbar()
{
    __syncthreads();
    if (threadIdx.x == 0) {
        __threadfence();
        unsigned g = atomicAdd(&g_bar_gen, 0u);
        if (atomicAdd(&g_bar_count, 1u) == NB1 - 1) {
            atomicExch(&g_bar_count, 0u);
            __threadfence();
            atomicAdd(&g_bar_gen, 1u);
        } else {
            while (atomicAdd(&g_bar_gen, 0u) == g) { }
        }
    }
    __syncthreads();
}

// ---------------------------------------------------------------------------
// K1: fused point pipeline — prep | gridbar | scatter | gridbar | resolve.
// Bodies identical to the R7 (22.2us) kernels.
// ---------------------------------------------------------------------------
__global__ __launch_bounds__(T1)
void k_points(const float* __restrict__ pp, const float* __restrict__ conf,
              const float* __restrict__ pose, const float* __restrict__ Kc)
{
    __shared__ float sred[T1 / 32];
    __shared__ float sbc[2];

    const int tid = threadIdx.x;
    const int gt  = blockIdx.x * T1 + tid;
    const int b   = blockIdx.x / BLKS_PER_B;
    const int p4  = gt * 4;
    const int i   = p4 - b * NN;
    const int lane = tid & 31, wid = tid >> 5;

    // ---------------- Phase A: zero planes; transform; block minmax
    {
        if (gt < PLANE / 4) {
            ((float4*)g_dep)[gt] = make_float4(0.f, 0.f, 0.f, 0.f);
            ((uint4*)g_key)[gt]  = make_uint4(0u, 0u, 0u, 0u);
        }

        const float* ppb = pp + (size_t)b * 7 * NN;
        float4 c0 = *(const float4*)(ppb + 0 * NN + i);
        float4 c1 = *(const float4*)(ppb + 1 * NN + i);
        float4 c2 = *(const float4*)(ppb + 2 * NN + i);
        float4 c3 = *(const float4*)(ppb + 3 * NN + i);
        float4 cf4 = *(const float4*)(conf + (size_t)b * NN + i);

        const float* P  = pose + b * 16;
        const float* Kb = Kc + b * 9;
        float fx = Kb[0], cx = Kb[2], fy = Kb[4], cy = Kb[5];

        float zz[4]; unsigned px[4];
        float mn = 3.0e38f, mx = 0.0f;
        float p0a[4] = {c0.x, c0.y, c0.z, c0.w};
        float p1a[4] = {c1.x, c1.y, c1.z, c1.w};
        float p2a[4] = {c2.x, c2.y, c2.z, c2.w};
        float p3a[4] = {c3.x, c3.y, c3.z, c3.w};
        float cfa[4] = {cf4.x, cf4.y, cf4.z, cf4.w};
#pragma unroll
        for (int j = 0; j < 4; j++) {
            float pc0 = P[0] * p0a[j] + P[1] * p1a[j] + P[2]  * p2a[j] + P[3]  * p3a[j];
            float pc1 = P[4] * p0a[j] + P[5] * p1a[j] + P[6]  * p2a[j] + P[7]  * p3a[j];
            float pc2 = P[8] * p0a[j] + P[9] * p1a[j] + P[10] * p2a[j] + P[11] * p3a[j];
            float z = fabsf(pc2);
            float xc = __fadd_rn(__fdiv_rn(__fmul_rn(pc0, fx), z), cx);
            float yc = __fadd_rn(__fdiv_rn(__fmul_rn(pc1, fy), z), cy);
            int x = (int)rintf(xc);
            int y = (int)rintf(yc);
            bool valid = !(x < 0 || x >= WW || y < 0 || y >= HH ||
                           z < ZNEAR || z > ZFAR || cfa[j] <= 0.0f);
            zz[j] = z;
            px[j] = valid ? (unsigned)(y * WW + x) : 0xFFFFFFFFu;
            if (valid) {
                float inv = __fdiv_rn(1.0f, z);
                mn = fminf(mn, inv);
                mx = fmaxf(mx, inv);
            }
        }
        *(float4*)(g_pz + p4) = make_float4(zz[0], zz[1], zz[2], zz[3]);
        *(uint4*)(g_pxy + p4) = make_uint4(px[0], px[1], px[2], px[3]);

#pragma unroll
        for (int s = 16; s > 0; s >>= 1) mn = fminf(mn, __shfl_down_sync(0xFFFFFFFFu, mn, s));
        if (lane == 0) sred[wid] = mn;
        __syncthreads();
        if (wid == 0) {
            float w = (lane < T1 / 32) ? sred[lane] : 3.0e38f;
#pragma unroll
            for (int s = 4; s > 0; s >>= 1) w = fminf(w, __shfl_down_sync(0xFFFFFFFFu, w, s));
            if (lane == 0) g_bmn[blockIdx.x] = w;
        }
        __syncthreads();
#pragma unroll
        for (int s = 16; s > 0; s >>= 1) mx = fmaxf(mx, __shfl_down_sync(0xFFFFFFFFu, mx, s));
        if (lane == 0) sred[wid] = mx;
        __syncthreads();
        if (wid == 0) {
            float w = (lane < T1 / 32) ? sred[lane] : 0.0f;
#pragma unroll
            for (int s = 4; s > 0; s >>= 1) w = fmaxf(w, __shfl_down_sync(0xFFFFFFFFu, w, s));
            if (lane == 0) g_bmx[blockIdx.x] = w;
        }
    }
    gridbar();

    // ---------------- Phase B: finalize batch minmax; scatter keys
    {
        if (wid < 2) {
            bool ismax = wid;
            float v = ismax ? 0.0f : 3.0e38f;
            for (int k = b * BLKS_PER_B + lane; k < (b + 1) * BLKS_PER_B; k += 32) {
                float u = ismax ? g_bmx[k] : g_bmn[k];
                v = ismax ? fmaxf(v, u) : fminf(v, u);
            }
#pragma unroll
            for (int s = 16; s > 0; s >>= 1) {
                float u = __shfl_down_sync(0xFFFFFFFFu, v, s);
                v = ismax ? fmaxf(v, u) : fminf(v, u);
            }
            if (lane == 0) sbc[wid] = ismax ? fmaxf(v, 1.0e-10f) : fminf(v, 1.0e10f);
        }
        __syncthreads();
        const float dmn = sbc[0];
        const float rng = __fsub_rn(sbc[1], dmn);

        uint4  px4 = *(const uint4*)(g_pxy + p4);
        float4 pz4 = *(const float4*)(g_pz + p4);
        unsigned pxa[4] = {px4.x, px4.y, px4.z, px4.w};
        float    zza[4] = {pz4.x, pz4.y, pz4.z, pz4.w};
#pragma unroll
        for (int j = 0; j < 4; j++) {
            if (pxa[j] == 0xFFFFFFFFu) continue;
            float inv = __fdiv_rn(1.0f, zza[j]);
            float t = __fmul_rn(__fdiv_rn(__fsub_rn(inv, dmn), rng), 63.0f);
            int dq = (int)t;
            unsigned key = ((((unsigned)dq) << 18) | (unsigned)(i + j)) + 1u;
            atomicMax(&g_key[b * HWp + pxa[j]], key);
        }
    }
    gridbar();

    // ---------------- Phase C: resolve winners
    {
        uint4  px4 = *(const uint4*)(g_pxy + p4);
        float4 pz4 = *(const float4*)(g_pz + p4);
        unsigned pxa[4] = {px4.x, px4.y, px4.z, px4.w};
        float    zza[4] = {pz4.x, pz4.y, pz4.z, pz4.w};

        unsigned ky[4];
#pragma unroll
        for (int j = 0; j < 4; j++)
            ky[j] = (pxa[j] != 0xFFFFFFFFu) ? g_key[b * HWp + pxa[j]] : 0u;

        const float* ppb = pp + (size_t)b * 7 * NN;
        float4 cf4 = *(const float4*)(conf + (size_t)b * NN + i);
        float4 r04 = *(const float4*)(ppb + 4 * NN + i);
        float4 r14 = *(const float4*)(ppb + 5 * NN + i);
        float4 r24 = *(const float4*)(ppb + 6 * NN + i);
        float cfa[4] = {cf4.x, cf4.y, cf4.z, cf4.w};
        float r0a[4] = {r04.x, r04.y, r04.z, r04.w};
        float r1a[4] = {r14.x, r14.y, r14.z, r14.w};
        float r2a[4] = {r24.x, r24.y, r24.z, r24.w};

#pragma unroll
        for (int j = 0; j < 4; j++) {
            if (pxa[j] == 0xFFFFFFFFu) continue;
            if (((ky[j] - 1u) & 0x3FFFFu) != (unsigned)(i + j)) continue;
            unsigned pxy = pxa[j];
            int y = (int)(pxy / WW), x = (int)(pxy - (unsigned)y * WW);
            int rf = HH - 1 - y;
            int pix = b * HWp + rf * WW + x;
            g_dep[pix] = zza[j];
            g_rec[pix] = make_float4(fmaxf(cfa[j], 0.0f), r0a[j], r1a[j], r2a[j]);
        }
    }
}

// ---------------------------------------------------------------------------
// Fill: one hole-fill iteration, 4 pixels (aligned quad) per thread.
// 0/1-mask conv (bit-identical to reference FMA loop); conv pads 0; values
// >= 0 so maxpool over in-bounds taps == max with zero floor.
// GATED=true: channel records valid only where depth>0 (iter-0 AoS).
// ---------------------------------------------------------------------------
template <bool GATED>
__device__ __forceinline__ void fill_quad(
    const float* __restrict__ dep, const float4* __restrict__ rec,
    int gy, int gx0, float* dout, float4* chout)
{
    float row[3][6];
#pragma unroll
    for (int r = 0; r < 3; r++) {
        int rr = gy - 1 + r;
        bool rv = (unsigned)rr < HH;
        float4 m = rv ? *(const float4*)(dep + rr * WW + gx0)
                      : make_float4(0.f, 0.f, 0.f, 0.f);
        row[r][1] = m.x; row[r][2] = m.y; row[r][3] = m.z; row[r][4] = m.w;
        row[r][0] = (rv && gx0 > 0)        ? dep[rr * WW + gx0 - 1] : 0.0f;
        row[r][5] = (rv && gx0 + 4 < WW)   ? dep[rr * WW + gx0 + 4] : 0.0f;
    }

    float4 myrec[4];
#pragma unroll
    for (int j = 0; j < 4; j++) myrec[j] = rec[gy * WW + gx0 + j];

#pragma unroll
    for (int j = 0; j < 4; j++) {
        float d0 = row[0][j], d1 = row[0][j+1], d2 = row[0][j+2];
        float d3 = row[1][j], d4 = row[1][j+1], d5 = row[1][j+2];
        float d6 = row[2][j], d7 = row[2][j+1], d8 = row[2][j+2];
        float s = d0 + d1 + d2 + d3 + d4 + d5 + d6 + d7 + d8;

        bool fill = false;
        if (s > 0.0f && d4 <= 0.0f) {
            float o0 = d0 + d3 + d6;
            float o1 = d6 + d7 + d8;
            float o2 = d2 + d5 + d8;
            float o3 = d0 + d1 + d2;
            float o4 = d3 + d6 + d7;
            float o5 = d5 + d7 + d8;
            float o6 = d1 + d2 + d5;
            float o7 = d0 + d1 + d3;
            float prod = ((((((o0 * o1) * o2) * o3) * o4) * o5) * o6) * o7;
            fill = fabsf(prod) > 1e-10f;
        }

        if (!fill) {
            dout[j] = d4;
            if (GATED && d4 <= 0.0f) chout[j] = make_float4(0.f, 0.f, 0.f, 0.f);
            else                     chout[j] = myrec[j];
        } else {
            float mxd = 0.0f;
            float4 cmx = make_float4(0.f, 0.f, 0.f, 0.f);
#pragma unroll
            for (int r = 0; r < 3; r++)
#pragma unroll
                for (int c = 0; c < 3; c++) {
                    float dv = row[r][j + c];
                    mxd = fmaxf(mxd, dv);
                    int rr = gy - 1 + r, cc = gx0 + j - 1 + c;
                    bool take = GATED ? (dv > 0.0f)
                                      : (((unsigned)rr < HH) & ((unsigned)cc < WW));
                    if (take) cmx = f4max(cmx, rec[rr * WW + cc]);
                }
            dout[j] = mxd; chout[j] = cmx;
        }
    }
}

// K2: iteration 1, AoS -> AoS
__global__ __launch_bounds__(256)
void k_fill_a()
{
    int q   = blockIdx.x * 256 + threadIdx.x;     // quad index
    int b   = q / (HWp / 4);
    int rem = q - b * (HWp / 4);
    int gy  = rem / (WW / 4);
    int gx0 = (rem - gy * (WW / 4)) * 4;

    float dout[4]; float4 chout[4];
    fill_quad<true>(g_dep + b * HWp, g_rec + b * HWp, gy, gx0, dout, chout);

    int base = b * HWp + gy * WW + gx0;
    *(float4*)(g_dep2 + base) = make_float4(dout[0], dout[1], dout[2], dout[3]);
#pragma unroll
    for (int j = 0; j < 4; j++) g_rec2[base + j] = chout[j];
}

// K3: iteration 2, AoS -> planar dst
__global__ __launch_bounds__(256)
void k_fill_b(float* __restrict__ dst)
{
    int q   = blockIdx.x * 256 + threadIdx.x;
    int b   = q / (HWp / 4);
    int rem = q - b * (HWp / 4);
    int gy  = rem / (WW / 4);
    int gx0 = (rem - gy * (WW / 4)) * 4;

    float dout[4]; float4 chout[4];
    fill_quad<false>(g_dep2 + b * HWp, g_rec2 + b * HWp, gy, gx0, dout, chout);

    int rc = gy * WW + gx0;
    *(float4*)(dst + b * HWp + rc) =
        make_float4(dout[0], dout[1], dout[2], dout[3]);
    *(float4*)(dst + PLANE + b * HWp + rc) =
        make_float4(chout[0].x, chout[1].x, chout[2].x, chout[3].x);
    *(float4*)(dst + 2 * PLANE + (b * 3 + 0) * HWp + rc) =
        make_float4(chout[0].y, chout[1].y, chout[2].y, chout[3].y);
    *(float4*)(dst + 2 * PLANE + (b * 3 + 1) * HWp + rc) =
        make_float4(chout[0].z, chout[1].z, chout[2].z, chout[3].z);
    *(float4*)(dst + 2 * PLANE + (b * 3 + 2) * HWp + rc) =
        make_float4(chout[0].w, chout[1].w, chout[2].w, chout[3].w);
}

// ---------------------------------------------------------------------------
extern "C" void kernel_launch(void* const* d_in, const int* in_sizes, int n_in,
                              void* d_out, int out_size)
{
    const float* pp      = (const float*)d_in[0];  // [b,7,n]
    const float* conf    = (const float*)d_in[1];  // [b,n]
    const float* pose    = (const float*)d_in[2];  // [b,4,4]
    const float* Kc      = (const float*)d_in[3];  // [b,3,3]
    (void)in_sizes; (void)n_in; (void)out_size;

    k_points<<<NB1, T1>>>(pp, conf, pose, Kc);
    k_fill_a<<<PLANE / 4 / 256, 256>>>();
    k_fill_b<<<PLANE / 4 / 256, 256>>>((float*)d_out);
}

// round 15
// speedup vs baseline: 1.2081x; 1.0860x over previous
#include <cuda_runtime.h>
#include <math.h>

// Problem-instance constants (setup_inputs: b=2, h=240, w=320, n=2*h*w)
#define BB 2
#define NN 153600
#define HH 240
#define WW 320
#define HWp (HH * WW)
#define PLANE (BB * HWp)
#define ZNEAR 0.1f
#define ZFAR 1000.0f

#define T1 256
#define NB1 300                 // 300 blocks * 256 thr * 4 pts = 307200 points
#define BLKS_PER_B (NB1 / BB)   // 150

// Scratch (__device__ globals; no allocations allowed)
__device__ __align__(16) unsigned g_key[PLANE];      // packed (dq<<18|i)+1
__device__ __align__(16) float    g_dep[PLANE];      // dense depth plane (iter0)
__device__ __align__(16) float4   g_rec[PLANE];      // cf,r,g,b (UNINIT for empty px)
__device__ __align__(16) float    g_dep2[PLANE];     // depth after iter1
__device__ __align__(16) float4   g_rec2[PLANE];     // channels after iter1
__device__ __align__(16) float    g_pz [BB * NN];
__device__ __align__(16) unsigned g_pxy[BB * NN];
__device__ float g_bmn[NB1];
__device__ float g_bmx[NB1];

__device__ __forceinline__ float4 f4max(float4 a, float4 b) {
    return make_float4(fmaxf(a.x, b.x), fmaxf(a.y, b.y),
                       fmaxf(a.z, b.z), fmaxf(a.w, b.w));
}

// ---------------------------------------------------------------------------
// K1: zero depth+key planes; transform 4 points/thread; per-block minmax.
// (R7 verbatim — best measured point config.)
// ---------------------------------------------------------------------------
__global__ __launch_bounds__(T1)
void k_prep(const float* __restrict__ pp, const float* __restrict__ conf,
            const float* __restrict__ pose, const float* __restrict__ Kc)
{
    __shared__ float sred[T1 / 32];
    const int tid = threadIdx.x;
    const int gt  = blockIdx.x * T1 + tid;

    if (gt < PLANE / 4) {
        ((float4*)g_dep)[gt] = make_float4(0.f, 0.f, 0.f, 0.f);
        ((uint4*)g_key)[gt]  = make_uint4(0u, 0u, 0u, 0u);
    }

    const int b  = blockIdx.x / BLKS_PER_B;
    const int p4 = gt * 4;
    const int i  = p4 - b * NN;

    const float* ppb = pp + (size_t)b * 7 * NN;
    float4 c0 = *(const float4*)(ppb + 0 * NN + i);
    float4 c1 = *(const float4*)(ppb + 1 * NN + i);
    float4 c2 = *(const float4*)(ppb + 2 * NN + i);
    float4 c3 = *(const float4*)(ppb + 3 * NN + i);
    float4 cf4 = *(const float4*)(conf + (size_t)b * NN + i);

    const float* P  = pose + b * 16;
    const float* Kb = Kc + b * 9;
    float fx = Kb[0], cx = Kb[2], fy = Kb[4], cy = Kb[5];

    float zz[4]; unsigned px[4];
    float mn = 3.0e38f, mx = 0.0f;
    float p0a[4] = {c0.x, c0.y, c0.z, c0.w};
    float p1a[4] = {c1.x, c1.y, c1.z, c1.w};
    float p2a[4] = {c2.x, c2.y, c2.z, c2.w};
    float p3a[4] = {c3.x, c3.y, c3.z, c3.w};
    float cfa[4] = {cf4.x, cf4.y, cf4.z, cf4.w};
#pragma unroll
    for (int j = 0; j < 4; j++) {
        float pc0 = P[0] * p0a[j] + P[1] * p1a[j] + P[2]  * p2a[j] + P[3]  * p3a[j];
        float pc1 = P[4] * p0a[j] + P[5] * p1a[j] + P[6]  * p2a[j] + P[7]  * p3a[j];
        float pc2 = P[8] * p0a[j] + P[9] * p1a[j] + P[10] * p2a[j] + P[11] * p3a[j];
        float z = fabsf(pc2);
        float xc = __fadd_rn(__fdiv_rn(__fmul_rn(pc0, fx), z), cx);
        float yc = __fadd_rn(__fdiv_rn(__fmul_rn(pc1, fy), z), cy);
        int x = (int)rintf(xc);
        int y = (int)rintf(yc);
        bool valid = !(x < 0 || x >= WW || y < 0 || y >= HH ||
                       z < ZNEAR || z > ZFAR || cfa[j] <= 0.0f);
        zz[j] = z;
        px[j] = valid ? (unsigned)(y * WW + x) : 0xFFFFFFFFu;
        if (valid) {
            float inv = __fdiv_rn(1.0f, z);
            mn = fminf(mn, inv);
            mx = fmaxf(mx, inv);
        }
    }
    *(float4*)(g_pz + p4) = make_float4(zz[0], zz[1], zz[2], zz[3]);
    *(uint4*)(g_pxy + p4) = make_uint4(px[0], px[1], px[2], px[3]);

    const int lane = tid & 31, wid = tid >> 5;
#pragma unroll
    for (int s = 16; s > 0; s >>= 1) mn = fminf(mn, __shfl_down_sync(0xFFFFFFFFu, mn, s));
    if (lane == 0) sred[wid] = mn;
    __syncthreads();
    if (wid == 0) {
        float w = (lane < T1 / 32) ? sred[lane] : 3.0e38f;
#pragma unroll
        for (int s = 4; s > 0; s >>= 1) w = fminf(w, __shfl_down_sync(0xFFFFFFFFu, w, s));
        if (lane == 0) g_bmn[blockIdx.x] = w;
    }
    __syncthreads();
#pragma unroll
    for (int s = 16; s > 0; s >>= 1) mx = fmaxf(mx, __shfl_down_sync(0xFFFFFFFFu, mx, s));
    if (lane == 0) sred[wid] = mx;
    __syncthreads();
    if (wid == 0) {
        float w = (lane < T1 / 32) ? sred[lane] : 0.0f;
#pragma unroll
        for (int s = 4; s > 0; s >>= 1) w = fmaxf(w, __shfl_down_sync(0xFFFFFFFFu, w, s));
        if (lane == 0) g_bmx[blockIdx.x] = w;
    }
}

// ---------------------------------------------------------------------------
// K2: finalize per-batch minmax; scatter atomicMax keys. (R7 verbatim.)
// ---------------------------------------------------------------------------
__global__ __launch_bounds__(T1)
void k_scatter()
{
    __shared__ float sbc[2];
    const int tid = threadIdx.x;
    const int b   = blockIdx.x / BLKS_PER_B;
    const int lane = tid & 31, wid = tid >> 5;

    if (wid < 2) {
        bool ismax = wid;
        float v = ismax ? 0.0f : 3.0e38f;
        for (int k = b * BLKS_PER_B + lane; k < (b + 1) * BLKS_PER_B; k += 32) {
            float u = ismax ? g_bmx[k] : g_bmn[k];
            v = ismax ? fmaxf(v, u) : fminf(v, u);
        }
#pragma unroll
        for (int s = 16; s > 0; s >>= 1) {
            float u = __shfl_down_sync(0xFFFFFFFFu, v, s);
            v = ismax ? fmaxf(v, u) : fminf(v, u);
        }
        if (lane == 0) sbc[wid] = ismax ? fmaxf(v, 1.0e-10f) : fminf(v, 1.0e10f);
    }
    __syncthreads();
    const float dmn = sbc[0];
    const float rng = __fsub_rn(sbc[1], dmn);

    const int gt = blockIdx.x * T1 + tid;
    const int p4 = gt * 4;
    const int i  = p4 - b * NN;
    uint4  px4 = *(const uint4*)(g_pxy + p4);
    float4 pz4 = *(const float4*)(g_pz + p4);
    unsigned pxa[4] = {px4.x, px4.y, px4.z, px4.w};
    float    zza[4] = {pz4.x, pz4.y, pz4.z, pz4.w};
#pragma unroll
    for (int j = 0; j < 4; j++) {
        if (pxa[j] == 0xFFFFFFFFu) continue;
        float inv = __fdiv_rn(1.0f, zza[j]);
        float t = __fmul_rn(__fdiv_rn(__fsub_rn(inv, dmn), rng), 63.0f);
        int dq = (int)t;
        unsigned key = ((((unsigned)dq) << 18) | (unsigned)(i + j)) + 1u;
        atomicMax(&g_key[b * HWp + pxa[j]], key);
    }
}

// ---------------------------------------------------------------------------
// K3: resolve — winners write depth + record float4 at flipped position.
// (R7 verbatim.)
// ---------------------------------------------------------------------------
__global__ __launch_bounds__(T1)
void k_resolve(const float* __restrict__ pp, const float* __restrict__ conf)
{
    const int tid = threadIdx.x;
    const int gt  = blockIdx.x * T1 + tid;
    const int b   = blockIdx.x / BLKS_PER_B;
    const int p4  = gt * 4;
    const int i   = p4 - b * NN;

    uint4  px4 = *(const uint4*)(g_pxy + p4);
    float4 pz4 = *(const float4*)(g_pz + p4);
    unsigned pxa[4] = {px4.x, px4.y, px4.z, px4.w};
    float    zza[4] = {pz4.x, pz4.y, pz4.z, pz4.w};

    unsigned ky[4];
#pragma unroll
    for (int j = 0; j < 4; j++)
        ky[j] = (pxa[j] != 0xFFFFFFFFu) ? g_key[b * HWp + pxa[j]] : 0u;

    const float* ppb = pp + (size_t)b * 7 * NN;
    float4 cf4 = *(const float4*)(conf + (size_t)b * NN + i);
    float4 r04 = *(const float4*)(ppb + 4 * NN + i);
    float4 r14 = *(const float4*)(ppb + 5 * NN + i);
    float4 r24 = *(const float4*)(ppb + 6 * NN + i);
    float cfa[4] = {cf4.x, cf4.y, cf4.z, cf4.w};
    float r0a[4] = {r04.x, r04.y, r04.z, r04.w};
    float r1a[4] = {r14.x, r14.y, r14.z, r14.w};
    float r2a[4] = {r24.x, r24.y, r24.z, r24.w};

#pragma unroll
    for (int j = 0; j < 4; j++) {
        if (pxa[j] == 0xFFFFFFFFu) continue;
        if (((ky[j] - 1u) & 0x3FFFFu) != (unsigned)(i + j)) continue;
        unsigned pxy = pxa[j];
        int y = (int)(pxy / WW), x = (int)(pxy - (unsigned)y * WW);
        int rf = HH - 1 - y;
        int pix = b * HWp + rf * WW + x;
        g_dep[pix] = zza[j];
        g_rec[pix] = make_float4(fmaxf(cfa[j], 0.0f), r0a[j], r1a[j], r2a[j]);
    }
}

// ---------------------------------------------------------------------------
// Fill core: one hole-fill iteration at one pixel, global reads, cheap conv.
// The 8 oriented filters are the reference's fixed 0/1 masks; each conv
// output is the k-ordered sum of a 3-tap subset of d9 (bit-identical to the
// FMA-with-zeros loop; validated rel_err 0.0). Conv pads 0; composited
// values >= 0, so maxpool over in-bounds taps == max with zero floor.
// GATED=true: channel records valid only where depth>0 (iter-0 AoS).
// ---------------------------------------------------------------------------
template <bool GATED>
__device__ __forceinline__ void fill_px(
    const float* __restrict__ dep, const float4* __restrict__ rec,
    int gy, int gx, float& dout, float4& chout)
{
    float d9[9];
#pragma unroll
    for (int dy = -1; dy <= 1; dy++)
#pragma unroll
        for (int dx = -1; dx <= 1; dx++) {
            int rr = gy + dy, cc = gx + dx;
            bool ok = ((unsigned)rr < HH) & ((unsigned)cc < WW);
            d9[(dy + 1) * 3 + (dx + 1)] = ok ? dep[rr * WW + cc] : 0.0f;
        }
    float d0 = d9[0], d1 = d9[1], d2 = d9[2];
    float d3 = d9[3], d4 = d9[4], d5 = d9[5];
    float d6 = d9[6], d7 = d9[7], d8 = d9[8];
    float s = d0 + d1 + d2 + d3 + d4 + d5 + d6 + d7 + d8;

    bool fill = false;
    if (s > 0.0f && d4 <= 0.0f) {
        float o0 = d0 + d3 + d6;
        float o1 = d6 + d7 + d8;
        float o2 = d2 + d5 + d8;
        float o3 = d0 + d1 + d2;
        float o4 = d3 + d6 + d7;
        float o5 = d5 + d7 + d8;
        float o6 = d1 + d2 + d5;
        float o7 = d0 + d1 + d3;
        float prod = ((((((o0 * o1) * o2) * o3) * o4) * o5) * o6) * o7;
        fill = fabsf(prod) > 1e-10f;
    }

    if (!fill) {
        dout = d4;
        if (GATED && d4 <= 0.0f) chout = make_float4(0.f, 0.f, 0.f, 0.f);
        else                     chout = rec[gy * WW + gx];
    } else {
        float mxd = 0.0f;                       // values >= 0; 0-floor exact
        float4 cmx = make_float4(0.f, 0.f, 0.f, 0.f);
#pragma unroll
        for (int dy = -1; dy <= 1; dy++)
#pragma unroll
            for (int dx = -1; dx <= 1; dx++) {
                float dv = d9[(dy + 1) * 3 + (dx + 1)];
                mxd = fmaxf(mxd, dv);
                bool take = GATED ? (dv > 0.0f)
                                  : (((unsigned)(gy + dy) < HH) &
                                     ((unsigned)(gx + dx) < WW));
                if (take) cmx = f4max(cmx, rec[(gy + dy) * WW + (gx + dx)]);
            }
        dout = mxd; chout = cmx;
    }
}

// K4a: iteration 1, AoS -> AoS (1 px/thread, 600 blocks — best measured occ)
__global__ __launch_bounds__(256)
void k_fill_a()
{
    int pix = blockIdx.x * 256 + threadIdx.x;
    int b   = pix / HWp;
    int rc  = pix - b * HWp;
    int gy  = rc / WW, gx = rc - gy * WW;

    float dout; float4 chout;
    fill_px<true>(g_dep + b * HWp, g_rec + b * HWp, gy, gx, dout, chout);
    g_dep2[pix] = dout;
    g_rec2[pix] = chout;
}

// K4b: iteration 2, AoS -> planar dst
__global__ __launch_bounds__(256)
void k_fill_b(float* __restrict__ dst)
{
    int pix = blockIdx.x * 256 + threadIdx.x;
    int b   = pix / HWp;
    int rc  = pix - b * HWp;
    int gy  = rc / WW, gx = rc - gy * WW;

    float dout; float4 chout;
    fill_px<false>(g_dep2 + b * HWp, g_rec2 + b * HWp, gy, gx, dout, chout);

    dst[b * HWp + rc]                       = dout;
    dst[PLANE + b * HWp + rc]               = chout.x;
    dst[2 * PLANE + (b * 3 + 0) * HWp + rc] = chout.y;
    dst[2 * PLANE + (b * 3 + 1) * HWp + rc] = chout.z;
    dst[2 * PLANE + (b * 3 + 2) * HWp + rc] = chout.w;
}

// ---------------------------------------------------------------------------
extern "C" void kernel_launch(void* const* d_in, const int* in_sizes, int n_in,
                              void* d_out, int out_size)
{
    const float* pp      = (const float*)d_in[0];  // [b,7,n]
    const float* conf    = (const float*)d_in[1];  // [b,n]
    const float* pose    = (const float*)d_in[2];  // [b,4,4]
    const float* Kc      = (const float*)d_in[3];  // [b,3,3]
    (void)in_sizes; (void)n_in; (void)out_size;

    k_prep   <<<NB1, T1>>>(pp, conf, pose, Kc);
    k_scatter<<<NB1, T1>>>();
    k_resolve<<<NB1, T1>>>(pp, conf);
    k_fill_a <<<PLANE / 256, 256>>>();
    k_fill_b <<<PLANE / 256, 256>>>((float*)d_out);
}

// round 16
// speedup vs baseline: 1.2210x; 1.0107x over previous
#include <cuda_runtime.h>
#include <math.h>

// Problem-instance constants (setup_inputs: b=2, h=240, w=320, n=2*h*w)
#define BB 2
#define NN 153600
#define HH 240
#define WW 320
#define HWp (HH * WW)
#define PLANE (BB * HWp)
#define ZNEAR 0.1f
#define ZFAR 1000.0f

#define T1 256
#define NB1 300                 // 300 blocks * 256 thr * 4 pts = 307200 points
#define BLKS_PER_B (NB1 / BB)   // 150

// Scratch (__device__ globals; no allocations allowed)
__device__ __align__(16) unsigned g_key[PLANE];      // packed (dq<<18|i)+1
__device__ __align__(16) float    g_dep[PLANE];      // dense depth plane (iter0)
__device__ __align__(16) float4   g_rec[PLANE];      // cf,r,g,b (UNINIT for empty px)
__device__ __align__(16) float    g_dep2[PLANE];     // depth after iter1
__device__ __align__(16) float4   g_rec2[PLANE];     // channels after iter1
__device__ __align__(16) float    g_pz [BB * NN];
__device__ __align__(16) unsigned g_pxy[BB * NN];
__device__ float g_bmn[NB1];
__device__ float g_bmx[NB1];

__device__ __forceinline__ float4 f4max(float4 a, float4 b) {
    return make_float4(fmaxf(a.x, b.x), fmaxf(a.y, b.y),
                       fmaxf(a.z, b.z), fmaxf(a.w, b.w));
}

// ---------------------------------------------------------------------------
// K1: zero depth+key planes; transform 4 points/thread; per-block minmax.
// Primary only (reads external inputs); triggers so K2 can pre-launch.
// ---------------------------------------------------------------------------
__global__ __launch_bounds__(T1)
void k_prep(const float* __restrict__ pp, const float* __restrict__ conf,
            const float* __restrict__ pose, const float* __restrict__ Kc)
{
    cudaTriggerProgrammaticLaunchCompletion();

    __shared__ float sred[T1 / 32];
    const int tid = threadIdx.x;
    const int gt  = blockIdx.x * T1 + tid;

    if (gt < PLANE / 4) {
        ((float4*)g_dep)[gt] = make_float4(0.f, 0.f, 0.f, 0.f);
        ((uint4*)g_key)[gt]  = make_uint4(0u, 0u, 0u, 0u);
    }

    const int b  = blockIdx.x / BLKS_PER_B;
    const int p4 = gt * 4;
    const int i  = p4 - b * NN;

    const float* ppb = pp + (size_t)b * 7 * NN;
    float4 c0 = *(const float4*)(ppb + 0 * NN + i);
    float4 c1 = *(const float4*)(ppb + 1 * NN + i);
    float4 c2 = *(const float4*)(ppb + 2 * NN + i);
    float4 c3 = *(const float4*)(ppb + 3 * NN + i);
    float4 cf4 = *(const float4*)(conf + (size_t)b * NN + i);

    const float* P  = pose + b * 16;
    const float* Kb = Kc + b * 9;
    float fx = Kb[0], cx = Kb[2], fy = Kb[4], cy = Kb[5];

    float zz[4]; unsigned px[4];
    float mn = 3.0e38f, mx = 0.0f;
    float p0a[4] = {c0.x, c0.y, c0.z, c0.w};
    float p1a[4] = {c1.x, c1.y, c1.z, c1.w};
    float p2a[4] = {c2.x, c2.y, c2.z, c2.w};
    float p3a[4] = {c3.x, c3.y, c3.z, c3.w};
    float cfa[4] = {cf4.x, cf4.y, cf4.z, cf4.w};
#pragma unroll
    for (int j = 0; j < 4; j++) {
        float pc0 = P[0] * p0a[j] + P[1] * p1a[j] + P[2]  * p2a[j] + P[3]  * p3a[j];
        float pc1 = P[4] * p0a[j] + P[5] * p1a[j] + P[6]  * p2a[j] + P[7]  * p3a[j];
        float pc2 = P[8] * p0a[j] + P[9] * p1a[j] + P[10] * p2a[j] + P[11] * p3a[j];
        float z = fabsf(pc2);
        float xc = __fadd_rn(__fdiv_rn(__fmul_rn(pc0, fx), z), cx);
        float yc = __fadd_rn(__fdiv_rn(__fmul_rn(pc1, fy), z), cy);
        int x = (int)rintf(xc);
        int y = (int)rintf(yc);
        bool valid = !(x < 0 || x >= WW || y < 0 || y >= HH ||
                       z < ZNEAR || z > ZFAR || cfa[j] <= 0.0f);
        zz[j] = z;
        px[j] = valid ? (unsigned)(y * WW + x) : 0xFFFFFFFFu;
        if (valid) {
            float inv = __fdiv_rn(1.0f, z);
            mn = fminf(mn, inv);
            mx = fmaxf(mx, inv);
        }
    }
    *(float4*)(g_pz + p4) = make_float4(zz[0], zz[1], zz[2], zz[3]);
    *(uint4*)(g_pxy + p4) = make_uint4(px[0], px[1], px[2], px[3]);

    const int lane = tid & 31, wid = tid >> 5;
#pragma unroll
    for (int s = 16; s > 0; s >>= 1) mn = fminf(mn, __shfl_down_sync(0xFFFFFFFFu, mn, s));
    if (lane == 0) sred[wid] = mn;
    __syncthreads();
    if (wid == 0) {
        float w = (lane < T1 / 32) ? sred[lane] : 3.0e38f;
#pragma unroll
        for (int s = 4; s > 0; s >>= 1) w = fminf(w, __shfl_down_sync(0xFFFFFFFFu, w, s));
        if (lane == 0) g_bmn[blockIdx.x] = w;
    }
    __syncthreads();
#pragma unroll
    for (int s = 16; s > 0; s >>= 1) mx = fmaxf(mx, __shfl_down_sync(0xFFFFFFFFu, mx, s));
    if (lane == 0) sred[wid] = mx;
    __syncthreads();
    if (wid == 0) {
        float w = (lane < T1 / 32) ? sred[lane] : 0.0f;
#pragma unroll
        for (int s = 4; s > 0; s >>= 1) w = fmaxf(w, __shfl_down_sync(0xFFFFFFFFu, w, s));
        if (lane == 0) g_bmx[blockIdx.x] = w;
    }
}

// ---------------------------------------------------------------------------
// K2: finalize per-batch minmax; scatter atomicMax keys.
// PDL secondary of prep: all reads depend on prep -> sync first.
// ---------------------------------------------------------------------------
__global__ __launch_bounds__(T1)
void k_scatter()
{
    cudaTriggerProgrammaticLaunchCompletion();
    cudaGridDependencySynchronize();

    __shared__ float sbc[2];
    const int tid = threadIdx.x;
    const int b   = blockIdx.x / BLKS_PER_B;
    const int lane = tid & 31, wid = tid >> 5;

    if (wid < 2) {
        bool ismax = wid;
        float v = ismax ? 0.0f : 3.0e38f;
        for (int k = b * BLKS_PER_B + lane; k < (b + 1) * BLKS_PER_B; k += 32) {
            float u = ismax ? g_bmx[k] : g_bmn[k];
            v = ismax ? fmaxf(v, u) : fminf(v, u);
        }
#pragma unroll
        for (int s = 16; s > 0; s >>= 1) {
            float u = __shfl_down_sync(0xFFFFFFFFu, v, s);
            v = ismax ? fmaxf(v, u) : fminf(v, u);
        }
        if (lane == 0) sbc[wid] = ismax ? fmaxf(v, 1.0e-10f) : fminf(v, 1.0e10f);
    }
    __syncthreads();
    const float dmn = sbc[0];
    const float rng = __fsub_rn(sbc[1], dmn);

    const int gt = blockIdx.x * T1 + tid;
    const int p4 = gt * 4;
    const int i  = p4 - b * NN;
    uint4  px4 = *(const uint4*)(g_pxy + p4);
    float4 pz4 = *(const float4*)(g_pz + p4);
    unsigned pxa[4] = {px4.x, px4.y, px4.z, px4.w};
    float    zza[4] = {pz4.x, pz4.y, pz4.z, pz4.w};
#pragma unroll
    for (int j = 0; j < 4; j++) {
        if (pxa[j] == 0xFFFFFFFFu) continue;
        float inv = __fdiv_rn(1.0f, zza[j]);
        float t = __fmul_rn(__fdiv_rn(__fsub_rn(inv, dmn), rng), 63.0f);
        int dq = (int)t;
        unsigned key = ((((unsigned)dq) << 18) | (unsigned)(i + j)) + 1u;
        atomicMax(&g_key[b * HWp + pxa[j]], key);
    }
}

// ---------------------------------------------------------------------------
// K3: resolve — winners write depth + record at flipped position.
// PDL secondary of scatter: input-only payload loads issued PRE-sync
// (pp/conf are external inputs); pz/pxy/key reads after sync.
// ---------------------------------------------------------------------------
__global__ __launch_bounds__(T1)
void k_resolve(const float* __restrict__ pp, const float* __restrict__ conf)
{
    cudaTriggerProgrammaticLaunchCompletion();

    const int tid = threadIdx.x;
    const int gt  = blockIdx.x * T1 + tid;
    const int b   = blockIdx.x / BLKS_PER_B;
    const int p4  = gt * 4;
    const int i   = p4 - b * NN;

    // Pre-sync prologue: external-input payload loads (independent of
    // everything upstream in this graph).
    const float* ppb = pp + (size_t)b * 7 * NN;
    float4 cf4 = *(const float4*)(conf + (size_t)b * NN + i);
    float4 r04 = *(const float4*)(ppb + 4 * NN + i);
    float4 r14 = *(const float4*)(ppb + 5 * NN + i);
    float4 r24 = *(const float4*)(ppb + 6 * NN + i);

    cudaGridDependencySynchronize();

    uint4  px4 = *(const uint4*)(g_pxy + p4);
    float4 pz4 = *(const float4*)(g_pz + p4);
    unsigned pxa[4] = {px4.x, px4.y, px4.z, px4.w};
    float    zza[4] = {pz4.x, pz4.y, pz4.z, pz4.w};

    unsigned ky[4];
#pragma unroll
    for (int j = 0; j < 4; j++)
        ky[j] = (pxa[j] != 0xFFFFFFFFu) ? g_key[b * HWp + pxa[j]] : 0u;

    float cfa[4] = {cf4.x, cf4.y, cf4.z, cf4.w};
    float r0a[4] = {r04.x, r04.y, r04.z, r04.w};
    float r1a[4] = {r14.x, r14.y, r14.z, r14.w};
    float r2a[4] = {r24.x, r24.y, r24.z, r24.w};

#pragma unroll
    for (int j = 0; j < 4; j++) {
        if (pxa[j] == 0xFFFFFFFFu) continue;
        if (((ky[j] - 1u) & 0x3FFFFu) != (unsigned)(i + j)) continue;
        unsigned pxy = pxa[j];
        int y = (int)(pxy / WW), x = (int)(pxy - (unsigned)y * WW);
        int rf = HH - 1 - y;
        int pix = b * HWp + rf * WW + x;
        g_dep[pix] = zza[j];
        g_rec[pix] = make_float4(fmaxf(cfa[j], 0.0f), r0a[j], r1a[j], r2a[j]);
    }
}

// ---------------------------------------------------------------------------
// Fill core: one hole-fill iteration at one pixel, global reads, cheap conv.
// (R15 verbatim — validated rel_err 0.0.)
// ---------------------------------------------------------------------------
template <bool GATED>
__device__ __forceinline__ void fill_px(
    const float* __restrict__ dep, const float4* __restrict__ rec,
    int gy, int gx, float& dout, float4& chout)
{
    float d9[9];
#pragma unroll
    for (int dy = -1; dy <= 1; dy++)
#pragma unroll
        for (int dx = -1; dx <= 1; dx++) {
            int rr = gy + dy, cc = gx + dx;
            bool ok = ((unsigned)rr < HH) & ((unsigned)cc < WW);
            d9[(dy + 1) * 3 + (dx + 1)] = ok ? dep[rr * WW + cc] : 0.0f;
        }
    float d0 = d9[0], d1 = d9[1], d2 = d9[2];
    float d3 = d9[3], d4 = d9[4], d5 = d9[5];
    float d6 = d9[6], d7 = d9[7], d8 = d9[8];
    float s = d0 + d1 + d2 + d3 + d4 + d5 + d6 + d7 + d8;

    bool fill = false;
    if (s > 0.0f && d4 <= 0.0f) {
        float o0 = d0 + d3 + d6;
        float o1 = d6 + d7 + d8;
        float o2 = d2 + d5 + d8;
        float o3 = d0 + d1 + d2;
        float o4 = d3 + d6 + d7;
        float o5 = d5 + d7 + d8;
        float o6 = d1 + d2 + d5;
        float o7 = d0 + d1 + d3;
        float prod = ((((((o0 * o1) * o2) * o3) * o4) * o5) * o6) * o7;
        fill = fabsf(prod) > 1e-10f;
    }

    if (!fill) {
        dout = d4;
        if (GATED && d4 <= 0.0f) chout = make_float4(0.f, 0.f, 0.f, 0.f);
        else                     chout = rec[gy * WW + gx];
    } else {
        float mxd = 0.0f;                       // values >= 0; 0-floor exact
        float4 cmx = make_float4(0.f, 0.f, 0.f, 0.f);
#pragma unroll
        for (int dy = -1; dy <= 1; dy++)
#pragma unroll
            for (int dx = -1; dx <= 1; dx++) {
                float dv = d9[(dy + 1) * 3 + (dx + 1)];
                mxd = fmaxf(mxd, dv);
                bool take = GATED ? (dv > 0.0f)
                                  : (((unsigned)(gy + dy) < HH) &
                                     ((unsigned)(gx + dx) < WW));
                if (take) cmx = f4max(cmx, rec[(gy + dy) * WW + (gx + dx)]);
            }
        dout = mxd; chout = cmx;
    }
}

// K4a: iteration 1, AoS -> AoS. PDL secondary of resolve.
__global__ __launch_bounds__(256)
void k_fill_a()
{
    cudaTriggerProgrammaticLaunchCompletion();
    cudaGridDependencySynchronize();

    int pix = blockIdx.x * 256 + threadIdx.x;
    int b   = pix / HWp;
    int rc  = pix - b * HWp;
    int gy  = rc / WW, gx = rc - gy * WW;

    float dout; float4 chout;
    fill_px<true>(g_dep + b * HWp, g_rec + b * HWp, gy, gx, dout, chout);
    g_dep2[pix] = dout;
    g_rec2[pix] = chout;
}

// K4b: iteration 2, AoS -> planar dst. PDL secondary of fill_a.
__global__ __launch_bounds__(256)
void k_fill_b(float* __restrict__ dst)
{
    cudaGridDependencySynchronize();

    int pix = blockIdx.x * 256 + threadIdx.x;
    int b   = pix / HWp;
    int rc  = pix - b * HWp;
    int gy  = rc / WW, gx = rc - gy * WW;

    float dout; float4 chout;
    fill_px<false>(g_dep2 + b * HWp, g_rec2 + b * HWp, gy, gx, dout, chout);

    dst[b * HWp + rc]                       = dout;
    dst[PLANE + b * HWp + rc]               = chout.x;
    dst[2 * PLANE + (b * 3 + 0) * HWp + rc] = chout.y;
    dst[2 * PLANE + (b * 3 + 1) * HWp + rc] = chout.z;
    dst[2 * PLANE + (b * 3 + 2) * HWp + rc] = chout.w;
}

// ---------------------------------------------------------------------------
// Launch helper: kernel with ProgrammaticStreamSerialization (PDL secondary).
// ---------------------------------------------------------------------------
static void launch_pdl(const void* func, dim3 grid, dim3 block, void** args)
{
    cudaLaunchConfig_t cfg = {};
    cfg.gridDim = grid;
    cfg.blockDim = block;
    cfg.dynamicSmemBytes = 0;
    cfg.stream = 0;
    cudaLaunchAttribute attr[1];
    attr[0].id = cudaLaunchAttributeProgrammaticStreamSerialization;
    attr[0].val.programmaticStreamSerializationAllowed = 1;
    cfg.attrs = attr;
    cfg.numAttrs = 1;
    cudaLaunchKernelExC(&cfg, func, args);
}

extern "C" void kernel_launch(void* const* d_in, const int* in_sizes, int n_in,
                              void* d_out, int out_size)
{
    const float* pp      = (const float*)d_in[0];  // [b,7,n]
    const float* conf    = (const float*)d_in[1];  // [b,n]
    const float* pose    = (const float*)d_in[2];  // [b,4,4]
    const float* Kc      = (const float*)d_in[3];  // [b,3,3]
    float* dst           = (float*)d_out;
    (void)in_sizes; (void)n_in; (void)out_size;

    // K1: ordinary launch (no upstream dependency inside the graph)
    k_prep<<<NB1, T1>>>(pp, conf, pose, Kc);

    // K2..K5: PDL secondaries — launch early, sync on predecessor in-kernel
    {
        void* args[] = {};
        launch_pdl((const void*)k_scatter, dim3(NB1), dim3(T1), args);
    }
    {
        void* args[] = {(void*)&pp, (void*)&conf};
        launch_pdl((const void*)k_resolve, dim3(NB1), dim3(T1), args);
    }
    {
        void* args[] = {};
        launch_pdl((const void*)k_fill_a, dim3(PLANE / 256), dim3(256), args);
    }
    {
        void* args[] = {(void*)&dst};
        launch_pdl((const void*)k_fill_b, dim3(PLANE / 256), dim3(256), args);
    }
}